// round 9
// baseline (speedup 1.0000x reference)
#include <cuda_runtime.h>
#include <cstdint>

// Problem constants
#define B_   4
#define T_   2048
#define C_   1024
#define H_   128
#define BT_  (B_ * T_)

// Scratch for Q, K, V projections (4 MB each) — __device__ globals per alloc rules.
__device__ float g_q[BT_ * H_];
__device__ float g_k[BT_ * H_];
__device__ float g_v[BT_ * H_];

// ---------------------------------------------------------------------------
// Kernel 1: fused QKV projection.  out[m, n] = sum_k x[m,k] * W[k,n]
// M = 8192, K = 1024, N = 128.  Block tile 64x128, 256 threads, 4x8 per thread.
// grid = (128 M-tiles, 3 weight matrices)
// ---------------------------------------------------------------------------
__global__ void __launch_bounds__(256) qkv_gemm_kernel(
    const float* __restrict__ x, const float* __restrict__ Wq,
    const float* __restrict__ Wk, const float* __restrict__ Wv)
{
    __shared__ float As[8][64];    // A tile transposed: As[k][m]
    __shared__ float Bs[8][128];   // B tile: Bs[k][n]

    const float* W;
    float* out;
    if (blockIdx.y == 0)      { W = Wq; out = g_q; }
    else if (blockIdx.y == 1) { W = Wk; out = g_k; }
    else                      { W = Wv; out = g_v; }

    const int t  = threadIdx.x;
    const int tx = t & 15;          // 16 col groups  -> cols tx*8 .. +7
    const int ty = t >> 4;          // 16 row groups  -> rows ty*4 .. +3
    const int m0 = blockIdx.x * 64;

    // A loader: 64 rows x 8 k = 512 floats, 2 per thread (float2)
    const int arow = t & 63;
    const int acol = (t >> 6) << 1;
    // B loader: 8 rows x 128 cols = 1024 floats, 4 per thread (float4)
    const int brow = t >> 5;
    const int bcol = (t & 31) << 2;

    float acc[4][8];
    #pragma unroll
    for (int i = 0; i < 4; i++)
        #pragma unroll
        for (int j = 0; j < 8; j++) acc[i][j] = 0.f;

    for (int k0 = 0; k0 < C_; k0 += 8) {
        float2 a2 = *(const float2*)(x + (size_t)(m0 + arow) * C_ + k0 + acol);
        float4 b4 = *(const float4*)(W + (size_t)(k0 + brow) * H_ + bcol);
        __syncthreads();   // previous tile fully consumed
        As[acol + 0][arow] = a2.x;
        As[acol + 1][arow] = a2.y;
        *(float4*)&Bs[brow][bcol] = b4;
        __syncthreads();
        #pragma unroll
        for (int kk = 0; kk < 8; kk++) {
            float a[4], b[8];
            *(float4*)&a[0] = *(const float4*)&As[kk][ty * 4];
            *(float4*)&b[0] = *(const float4*)&Bs[kk][tx * 8];
            *(float4*)&b[4] = *(const float4*)&Bs[kk][tx * 8 + 4];
            #pragma unroll
            for (int i = 0; i < 4; i++)
                #pragma unroll
                for (int j = 0; j < 8; j++)
                    acc[i][j] = fmaf(a[i], b[j], acc[i][j]);
        }
    }

    #pragma unroll
    for (int i = 0; i < 4; i++) {
        size_t ro = (size_t)(m0 + ty * 4 + i) * H_ + tx * 8;
        *(float4*)(out + ro)     = make_float4(acc[i][0], acc[i][1], acc[i][2], acc[i][3]);
        *(float4*)(out + ro + 4) = make_float4(acc[i][4], acc[i][5], acc[i][6], acc[i][7]);
    }
}

// ---------------------------------------------------------------------------
// Kernel 2: flash attention, fp32, causal.
// BM = 32 queries / block-pass, BN = 64 keys / tile, 256 threads.
// Each block handles query tiles (blockIdx.x) and (63 - blockIdx.x) so causal
// work is balanced (~33 key tiles per block).
// Thread (tx, ty): S frag 2x4 (rows ty*2+r, cols tx*4+c),
//                  O frag 2x8 (rows ty*2+r, cols tx*8..+7).
// K tile uses a 16B-granule XOR swizzle (g ^ ((row>>2)&7)) so the 16 lanes of
// a half-warp (row stride 4) hit distinct bank groups.
// ---------------------------------------------------------------------------
__global__ void __launch_bounds__(256) attn_kernel(float* __restrict__ out)
{
    extern __shared__ float sm[];
    float* Qs = sm;                    // 32 * 128
    float* Ks = Qs + 32 * 128;         // 64 * 128 (swizzled)
    float* Vs = Ks + 64 * 128;         // 64 * 128
    float* Ps = Vs + 64 * 128;         // 32 * 64

    const int b  = blockIdx.y;
    const int t  = threadIdx.x;
    const int tx = t & 15;
    const int ty = t >> 4;
    const float scale = 0.03125f;      // C^-0.5, C = 1024

    #pragma unroll 1
    for (int pass = 0; pass < 2; pass++) {
        const int qt = (pass == 0) ? (int)blockIdx.x : 63 - (int)blockIdx.x;
        const int ntiles = (qt >> 1) + 1;
        const size_t qbase = ((size_t)b * T_ + qt * 32) * H_;

        __syncthreads();   // all reads of smem from previous pass done
        // Load Q tile (pre-scaled): 32x128 floats
        for (int i = t; i < 32 * 32; i += 256) {
            int row = i >> 5, c4 = (i & 31) << 2;
            float4 q = *(const float4*)(g_q + qbase + (size_t)row * H_ + c4);
            q.x *= scale; q.y *= scale; q.z *= scale; q.w *= scale;
            *(float4*)&Qs[row * 128 + c4] = q;
        }

        float m[2] = {-1e30f, -1e30f};
        float l[2] = {0.f, 0.f};
        float o[2][8];
        #pragma unroll
        for (int r = 0; r < 2; r++)
            #pragma unroll
            for (int c = 0; c < 8; c++) o[r][c] = 0.f;

        #pragma unroll 1
        for (int j = 0; j < ntiles; j++) {
            __syncthreads();   // previous tile's Ks/Vs/Ps reads done (also orders Qs writes)
            const size_t kb = ((size_t)b * T_ + j * 64) * H_;
            for (int i = t; i < 64 * 32; i += 256) {
                int row = i >> 5, g = i & 31;
                int gs = g ^ ((row >> 2) & 7);
                float4 k4 = *(const float4*)(g_k + kb + (size_t)row * H_ + (g << 2));
                *(float4*)&Ks[row * 128 + (gs << 2)] = k4;
                float4 v4 = *(const float4*)(g_v + kb + (size_t)row * H_ + (g << 2));
                *(float4*)&Vs[row * 128 + (g << 2)] = v4;
            }
            __syncthreads();

            // ---- S = Q K^T (scaled) ----
            float s[2][4] = {{0.f,0.f,0.f,0.f},{0.f,0.f,0.f,0.f}};
            #pragma unroll 4
            for (int d = 0; d < 128; d += 4) {
                float4 qv0 = *(const float4*)&Qs[(ty * 2 + 0) * 128 + d];
                float4 qv1 = *(const float4*)&Qs[(ty * 2 + 1) * 128 + d];
                const int gs = (((d >> 2) ^ (tx & 7)) << 2);
                float4 kv[4];
                #pragma unroll
                for (int c = 0; c < 4; c++)
                    kv[c] = *(const float4*)&Ks[(tx * 4 + c) * 128 + gs];
                #pragma unroll
                for (int c = 0; c < 4; c++) {
                    s[0][c] = fmaf(qv0.x, kv[c].x, s[0][c]);
                    s[0][c] = fmaf(qv0.y, kv[c].y, s[0][c]);
                    s[0][c] = fmaf(qv0.z, kv[c].z, s[0][c]);
                    s[0][c] = fmaf(qv0.w, kv[c].w, s[0][c]);
                    s[1][c] = fmaf(qv1.x, kv[c].x, s[1][c]);
                    s[1][c] = fmaf(qv1.y, kv[c].y, s[1][c]);
                    s[1][c] = fmaf(qv1.z, kv[c].z, s[1][c]);
                    s[1][c] = fmaf(qv1.w, kv[c].w, s[1][c]);
                }
            }

            // ---- causal mask (only the last tile touches the diagonal) ----
            if (j == ntiles - 1) {
                const int kcol = j * 64 + tx * 4;
                const int qrow = qt * 32 + ty * 2;
                #pragma unroll
                for (int r = 0; r < 2; r++)
                    #pragma unroll
                    for (int c = 0; c < 4; c++)
                        if (kcol + c > qrow + r) s[r][c] = -1e30f;
            }

            // ---- online softmax (rows owned by 16-lane half-warp groups) ----
            #pragma unroll
            for (int r = 0; r < 2; r++) {
                float mx = fmaxf(fmaxf(s[r][0], s[r][1]), fmaxf(s[r][2], s[r][3]));
                #pragma unroll
                for (int off = 1; off < 16; off <<= 1)
                    mx = fmaxf(mx, __shfl_xor_sync(0xffffffffu, mx, off));
                float mnew  = fmaxf(m[r], mx);
                float alpha = __expf(m[r] - mnew);
                m[r] = mnew;
                float p0 = __expf(s[r][0] - mnew);
                float p1 = __expf(s[r][1] - mnew);
                float p2 = __expf(s[r][2] - mnew);
                float p3 = __expf(s[r][3] - mnew);
                float ls = (p0 + p1) + (p2 + p3);
                #pragma unroll
                for (int off = 1; off < 16; off <<= 1)
                    ls += __shfl_xor_sync(0xffffffffu, ls, off);
                l[r] = l[r] * alpha + ls;
                #pragma unroll
                for (int c = 0; c < 8; c++) o[r][c] *= alpha;
                *(float4*)&Ps[(ty * 2 + r) * 64 + tx * 4] = make_float4(p0, p1, p2, p3);
            }
            __syncthreads();

            // ---- O += P @ V ----
            #pragma unroll 4
            for (int n4 = 0; n4 < 16; n4++) {
                float4 pa = *(const float4*)&Ps[(ty * 2 + 0) * 64 + (n4 << 2)];
                float4 pb = *(const float4*)&Ps[(ty * 2 + 1) * 64 + (n4 << 2)];
                #pragma unroll
                for (int nn = 0; nn < 4; nn++) {
                    const float* vrow = &Vs[(n4 * 4 + nn) * 128 + tx * 8];
                    float4 va = *(const float4*)(vrow);
                    float4 vb = *(const float4*)(vrow + 4);
                    float pv[2] = { (&pa.x)[nn], (&pb.x)[nn] };
                    #pragma unroll
                    for (int r = 0; r < 2; r++) {
                        o[r][0] = fmaf(pv[r], va.x, o[r][0]);
                        o[r][1] = fmaf(pv[r], va.y, o[r][1]);
                        o[r][2] = fmaf(pv[r], va.z, o[r][2]);
                        o[r][3] = fmaf(pv[r], va.w, o[r][3]);
                        o[r][4] = fmaf(pv[r], vb.x, o[r][4]);
                        o[r][5] = fmaf(pv[r], vb.y, o[r][5]);
                        o[r][6] = fmaf(pv[r], vb.z, o[r][6]);
                        o[r][7] = fmaf(pv[r], vb.w, o[r][7]);
                    }
                }
            }
        }

        // ---- epilogue: normalize and store ----
        #pragma unroll
        for (int r = 0; r < 2; r++) {
            float inv = 1.0f / l[r];
            size_t ro = ((size_t)b * T_ + qt * 32 + ty * 2 + r) * H_ + tx * 8;
            *(float4*)(out + ro)     = make_float4(o[r][0]*inv, o[r][1]*inv, o[r][2]*inv, o[r][3]*inv);
            *(float4*)(out + ro + 4) = make_float4(o[r][4]*inv, o[r][5]*inv, o[r][6]*inv, o[r][7]*inv);
        }
    }
}

// ---------------------------------------------------------------------------
// Launch
// ---------------------------------------------------------------------------
extern "C" void kernel_launch(void* const* d_in, const int* in_sizes, int n_in,
                              void* d_out, int out_size)
{
    (void)in_sizes; (void)n_in; (void)out_size;
    const float* x  = (const float*)d_in[0];
    const float* Wq = (const float*)d_in[1];
    const float* Wk = (const float*)d_in[2];
    const float* Wv = (const float*)d_in[3];
    float* out = (float*)d_out;

    // QKV projection: 128 M-tiles x 3 matrices
    qkv_gemm_kernel<<<dim3(128, 3), 256>>>(x, Wq, Wk, Wv);

    // Flash attention: 32 balanced query-tile pairs x 4 batches
    const int smem_bytes = (32 * 128 + 64 * 128 + 64 * 128 + 32 * 64) * (int)sizeof(float); // 90112
    cudaFuncSetAttribute(attn_kernel, cudaFuncAttributeMaxDynamicSharedMemorySize, smem_bytes);
    attn_kernel<<<dim3(32, B_), 256, smem_bytes>>>(out);
}